// round 1
// baseline (speedup 1.0000x reference)
#include <cuda_runtime.h>
#include <cstdint>

// Shapes (fixed by the problem): B=4, N=50000
//  f1: [B,64,56,56]  f2: [B,128,28,28]  f3: [B,256,14,14]  f4: [B,512,7,7]
//  out: [B,N,963]  (3 coord + 64 + 128 + 256 + 512)

#define BMAX 4

// Transposed feature scratch: [b][x][y][c] layout (channel-contiguous per texel)
__device__ float g_t1[BMAX * 56 * 56 * 64];   // 802816
__device__ float g_t2[BMAX * 28 * 28 * 128];  // 401408
__device__ float g_t3[BMAX * 14 * 14 * 256];  // 200704
__device__ float g_t4[BMAX * 7  * 7  * 512];  // 100352

// ---------------------------------------------------------------------------
// Transpose [B,C,S,S] -> [B,S,S,C].  Writes coalesced; reads strided (L2-hit).
// ---------------------------------------------------------------------------
__global__ void transpose_kernel(const float* __restrict__ in,
                                 float* __restrict__ out,
                                 int C, int S, int total) {
    int idx = blockIdx.x * blockDim.x + threadIdx.x;
    if (idx >= total) return;
    int c = idx % C;
    int y = (idx / C) % S;
    int x = (idx / (C * S)) % S;
    int b = idx / (C * S * S);
    out[idx] = in[((b * C + c) * S + x) * S + y];
}

// ---------------------------------------------------------------------------
// Main gather: one block per (point n, batch b).
// Threads 0..3 compute the per-level bilinear params into smem, then all 256
// threads sweep the 963 output channels with coalesced loads and stores.
// ---------------------------------------------------------------------------
__global__ __launch_bounds__(256)
void gather_kernel(const float* __restrict__ coord,   // [N,3] (batch 0's coords)
                   const float* __restrict__ t1,
                   const float* __restrict__ t2,
                   const float* __restrict__ t3,
                   const float* __restrict__ t4,
                   float* __restrict__ out,
                   int N) {
    const int n = blockIdx.x;
    const int b = blockIdx.y;
    const int tid = threadIdx.x;

    __shared__ float sw[4][4];   // [level][w11,w21,w12,w22]
    __shared__ int   so[4][4];   // [level][o11,o21,o12,o22] element offsets (incl. batch)
    __shared__ float scoord[3];

    if (tid < 4) {
        const float X = coord[3 * n + 0];
        const float Y = coord[3 * n + 1];
        const float Z = coord[3 * n + 2];
        const float negZ = -Z;
        float h = 250.0f * (-Y) / negZ + 112.0f;
        h = fminf(fmaxf(h, 0.0f), 223.0f);
        float w = 250.0f * X / negZ + 112.0f;
        w = fminf(fmaxf(w, 0.0f), 223.0f);

        const int   Ss[4]    = {56, 28, 14, 7};
        const float invsc[4] = {1.0f / 4.0f, 1.0f / 8.0f, 1.0f / 16.0f, 1.0f / 32.0f};
        const int   Cs[4]    = {64, 128, 256, 512};

        const int L = tid;
        const int S = Ss[L];
        const int C = Cs[L];
        float x = fminf(h * invsc[L], (float)(S - 1));   // h/scale, clipped to [0, S-1]
        float y = fminf(w * invsc[L], (float)(S - 1));
        // (>= 0 guaranteed since h,w >= 0)
        const float x1f = floorf(x), x2f = ceilf(x);
        const float y1f = floorf(y), y2f = ceilf(y);
        const int x1 = (int)x1f, x2 = (int)x2f;
        const int y1 = (int)y1f, y2 = (int)y2f;
        const float ax2 = x2f - x, ax1 = x - x1f;   // weights along x
        const float ay2 = y2f - y, ay1 = y - y1f;   // weights along y

        const int base = b * S * S * C;
        so[L][0] = base + (x1 * S + y1) * C;   // Q11
        so[L][1] = base + (x2 * S + y1) * C;   // Q21
        so[L][2] = base + (x1 * S + y2) * C;   // Q12
        so[L][3] = base + (x2 * S + y2) * C;   // Q22
        sw[L][0] = ax2 * ay2;
        sw[L][1] = ax1 * ay2;
        sw[L][2] = ax2 * ay1;
        sw[L][3] = ax1 * ay1;
    }
    if (tid < 3) scoord[tid] = coord[3 * n + tid];
    __syncthreads();

    float* o = out + ((size_t)b * N + n) * 963;

    #pragma unroll 4
    for (int ch = tid; ch < 963; ch += 256) {
        float v;
        if (ch < 3) {
            v = scoord[ch];
        } else {
            int L, c;
            const float* __restrict__ t;
            if (ch < 67)       { L = 0; c = ch - 3;   t = t1; }
            else if (ch < 195) { L = 1; c = ch - 67;  t = t2; }
            else if (ch < 451) { L = 2; c = ch - 195; t = t3; }
            else               { L = 3; c = ch - 451; t = t4; }
            v = sw[L][0] * t[so[L][0] + c]
              + sw[L][1] * t[so[L][1] + c]
              + sw[L][2] * t[so[L][2] + c]
              + sw[L][3] * t[so[L][3] + c];
        }
        o[ch] = v;
    }
}

// ---------------------------------------------------------------------------
extern "C" void kernel_launch(void* const* d_in, const int* in_sizes, int n_in,
                              void* d_out, int out_size) {
    const float* inputs = (const float*)d_in[0];  // [B,N,3]; coord = inputs[0]
    const float* f1 = (const float*)d_in[1];
    const float* f2 = (const float*)d_in[2];
    const float* f3 = (const float*)d_in[3];
    const float* f4 = (const float*)d_in[4];
    float* out = (float*)d_out;

    const int B = in_sizes[1] / (64 * 56 * 56);
    const int N = in_sizes[0] / (3 * B);

    float* t1; float* t2; float* t3; float* t4;
    cudaGetSymbolAddress((void**)&t1, g_t1);
    cudaGetSymbolAddress((void**)&t2, g_t2);
    cudaGetSymbolAddress((void**)&t3, g_t3);
    cudaGetSymbolAddress((void**)&t4, g_t4);

    const int thr = 256;
    {
        int total = B * 64 * 56 * 56;
        transpose_kernel<<<(total + thr - 1) / thr, thr>>>(f1, t1, 64, 56, total);
    }
    {
        int total = B * 128 * 28 * 28;
        transpose_kernel<<<(total + thr - 1) / thr, thr>>>(f2, t2, 128, 28, total);
    }
    {
        int total = B * 256 * 14 * 14;
        transpose_kernel<<<(total + thr - 1) / thr, thr>>>(f3, t3, 256, 14, total);
    }
    {
        int total = B * 512 * 7 * 7;
        transpose_kernel<<<(total + thr - 1) / thr, thr>>>(f4, t4, 512, 7, total);
    }

    dim3 grid(N, B);
    gather_kernel<<<grid, 256>>>(inputs, t1, t2, t3, t4, out, N);
}